// round 5
// baseline (speedup 1.0000x reference)
#include <cuda_runtime.h>
#include <cuda_bf16.h>
#include <stdint.h>

// units2indices: 80M fp32 bipolar {-1,+1} -> 8M codebook index VALUES
// stored as float32 (harness __output__ dtype is float32 — R1-R3 finding).
// Groups of num_bits=10, first element is MSB.
//
// Bit rule: fp32 +1.0 sign bit 0 -> bit 1; -1.0 sign bit 1 -> bit 0.
//
// HBM-bound streaming: 4 groups per thread = 40 floats = 10x LDG.128
// (front-batched, high MLP), one STG.128 out. Streaming cache hints
// (__ldcs/__stcs) since there is zero reuse.

__global__ __launch_bounds__(256)
void units2indices_quads_f32(const uint4* __restrict__ in4,
                             float4* __restrict__ out4,
                             int n_quads)
{
    int t = blockIdx.x * blockDim.x + threadIdx.x;
    if (t >= n_quads) return;

    // 10 x uint4 = 40 words = 4 groups of 10
    const uint4* p = in4 + (size_t)t * 10;
    uint4 v0 = __ldcs(p + 0);
    uint4 v1 = __ldcs(p + 1);
    uint4 v2 = __ldcs(p + 2);
    uint4 v3 = __ldcs(p + 3);
    uint4 v4 = __ldcs(p + 4);
    uint4 v5 = __ldcs(p + 5);
    uint4 v6 = __ldcs(p + 6);
    uint4 v7 = __ldcs(p + 7);
    uint4 v8 = __ldcs(p + 8);
    uint4 v9 = __ldcs(p + 9);

    unsigned w[40] = {
        v0.x, v0.y, v0.z, v0.w,  v1.x, v1.y, v1.z, v1.w,
        v2.x, v2.y, v2.z, v2.w,  v3.x, v3.y, v3.z, v3.w,
        v4.x, v4.y, v4.z, v4.w,  v5.x, v5.y, v5.z, v5.w,
        v6.x, v6.y, v6.z, v6.w,  v7.x, v7.y, v7.z, v7.w,
        v8.x, v8.y, v8.z, v8.w,  v9.x, v9.y, v9.z, v9.w
    };

    int idx[4] = {0, 0, 0, 0};
    #pragma unroll
    for (int g = 0; g < 4; g++) {
        #pragma unroll
        for (int i = 0; i < 10; i++)
            idx[g] = (idx[g] << 1) | (int)(1u - (w[g * 10 + i] >> 31));
    }

    float4 r = make_float4((float)idx[0], (float)idx[1],
                           (float)idx[2], (float)idx[3]);
    __stcs(out4 + t, r);
}

// Generic fallback (num_bits != 10, misalignment, or tail groups).
__global__ __launch_bounds__(256)
void units2indices_generic_f32(const unsigned* __restrict__ in,
                               float* __restrict__ out,
                               int n_groups, int num_bits, int g_start)
{
    int g = g_start + blockIdx.x * blockDim.x + threadIdx.x;
    if (g >= n_groups) return;

    const unsigned* p = in + (size_t)g * num_bits;
    int idx = 0;
    for (int i = 0; i < num_bits; i++)
        idx = (idx << 1) | (int)(1u - (p[i] >> 31));
    out[g] = (float)idx;
}

extern "C" void kernel_launch(void* const* d_in, const int* in_sizes, int n_in,
                              void* d_out, int out_size)
{
    // Input tensor = largest buffer (robust to ordering / scalar inputs).
    int imax = 0;
    for (int i = 1; i < n_in; i++)
        if (in_sizes[i] > in_sizes[imax]) imax = i;

    const unsigned* in = (const unsigned*)d_in[imax];
    float* out = (float*)d_out;

    long long n_total = (long long)in_sizes[imax];
    int num_bits = (out_size > 0) ? (int)(n_total / (long long)out_size) : 10;
    if (num_bits <= 0) num_bits = 10;

    int threads = 256;
    bool in_al16  = (((uintptr_t)in)  & 15u) == 0;
    bool out_al16 = (((uintptr_t)out) & 15u) == 0;

    if (num_bits == 10 && in_al16 && out_al16) {
        int n_quads = out_size / 4;
        if (n_quads > 0) {
            int blocks = (n_quads + threads - 1) / threads;
            units2indices_quads_f32<<<blocks, threads>>>(
                (const uint4*)in, (float4*)out, n_quads);
        }
        int tail = out_size & 3;
        if (tail) {
            units2indices_generic_f32<<<1, 32>>>(
                in, out, out_size, 10, out_size - tail);
        }
    } else {
        int blocks = (out_size + threads - 1) / threads;
        units2indices_generic_f32<<<blocks, threads>>>(
            in, out, out_size, num_bits, 0);
    }
}

// round 6
// speedup vs baseline: 1.1518x; 1.1518x over previous
#include <cuda_runtime.h>
#include <cuda_bf16.h>
#include <stdint.h>

// units2indices: 80M fp32 bipolar {-1,+1} -> 8M codebook index VALUES stored
// as float32 (harness __output__ dtype is float32). Groups of num_bits=10,
// first element is MSB.
//
// R5 lesson: per-thread-strided uint4 loads destroy coalescing (each warp
// LDG touches 20-40 lines). This version uses lane-contiguous scalar loads
// (1 line per warp LDG) + __ballot_sync to transpose sign bits into packed
// masks, then funnel-shift + bit-reverse to emit groups.
//
// Block = 256 threads, handles 5120 floats = 512 groups.
// 80,000,000 / 5120 = 15625 blocks exactly (no tail for the bench shape).

__global__ __launch_bounds__(256)
void units2indices_ballot(const unsigned* __restrict__ in,
                          float2* __restrict__ out2)
{
    __shared__ unsigned m[161];   // 160 masks + pad word

    const unsigned tid  = threadIdx.x;
    const unsigned lane = tid & 31u;
    const unsigned warp = tid >> 5;

    const unsigned* p = in + (size_t)blockIdx.x * 5120;

    if (tid == 0) m[160] = 0u;

    // Phase 1: coalesced streaming loads + ballot sign-transpose.
    #pragma unroll
    for (int it = 0; it < 20; it++) {
        unsigned w = __ldcs(p + it * 256 + tid);
        // +1.0f -> sign 0 -> bit 1 ; -1.0f -> sign 1 -> bit 0
        unsigned mask = __ballot_sync(0xFFFFFFFFu, !(w >> 31));
        if (lane == 0) m[it * 8 + warp] = mask;
    }
    __syncthreads();

    // Phase 2: thread t emits groups 2t and 2t+1 (bits [20t, 20t+20)).
    const unsigned b   = 20u * tid;
    const unsigned w0  = m[b >> 5];
    const unsigned w1  = m[(b >> 5) + 1];
    const unsigned bits = __funnelshift_r(w0, w1, b & 31u);

    // First element of a group is the MSB -> bit-reverse the 10-bit field.
    unsigned g0 = __brev(bits & 0x3FFu) >> 22;
    unsigned g1 = __brev((bits >> 10) & 0x3FFu) >> 22;

    __stcs(out2 + (size_t)blockIdx.x * 256 + tid,
           make_float2((float)g0, (float)g1));
}

// Generic fallback (num_bits != 10, odd shapes, tails).
__global__ __launch_bounds__(256)
void units2indices_generic_f32(const unsigned* __restrict__ in,
                               float* __restrict__ out,
                               int n_groups, int num_bits, int g_start)
{
    int g = g_start + blockIdx.x * blockDim.x + threadIdx.x;
    if (g >= n_groups) return;

    const unsigned* p = in + (size_t)g * num_bits;
    int idx = 0;
    for (int i = 0; i < num_bits; i++)
        idx = (idx << 1) | (int)(1u - (p[i] >> 31));
    out[g] = (float)idx;
}

extern "C" void kernel_launch(void* const* d_in, const int* in_sizes, int n_in,
                              void* d_out, int out_size)
{
    // Input tensor = largest buffer (robust to ordering / scalar inputs).
    int imax = 0;
    for (int i = 1; i < n_in; i++)
        if (in_sizes[i] > in_sizes[imax]) imax = i;

    const unsigned* in = (const unsigned*)d_in[imax];
    float* out = (float*)d_out;

    long long n_total = (long long)in_sizes[imax];
    int num_bits = (out_size > 0) ? (int)(n_total / (long long)out_size) : 10;
    if (num_bits <= 0) num_bits = 10;

    if (num_bits == 10) {
        int full_blocks = out_size / 512;             // 512 groups per block
        if (full_blocks > 0) {
            units2indices_ballot<<<full_blocks, 256>>>(in, (float2*)out);
        }
        int done = full_blocks * 512;
        int rem = out_size - done;
        if (rem > 0) {
            int blocks = (rem + 255) / 256;
            units2indices_generic_f32<<<blocks, 256>>>(
                in, out, out_size, 10, done);
        }
    } else {
        int blocks = (out_size + 255) / 256;
        units2indices_generic_f32<<<blocks, 256>>>(
            in, out, out_size, num_bits, 0);
    }
}